// round 5
// baseline (speedup 1.0000x reference)
#include <cuda_runtime.h>
#include <cuda_bf16.h>
#include <stdint.h>
#include <math.h>

#define CBN  6
#define CSZ  1024
#define TPB  256
#define RPC  128          // rows per CTA
#define EPS  0.125f       // trigger margin: covers bf16-MMA error + tie window

__device__ double g_part[CBN * 256];
__device__ unsigned int g_ctr = 0;

struct __align__(16) Smem {
    float4 craw[2 * CSZ];          // 32KB exact fp32 codebook
    __nv_bfloat16 cbf[CSZ * 8];    // 16KB bf16 codebook
    float c2arr[CSZ];              //  4KB exact c2
    float Lsh[CSZ];                //  4KB L = log2pmf/lambda
    float p2sh[CSZ];               //  4KB log2pmf
    float4 xfp[RPC * 2];           //  4KB exact fp32 x rows
    __nv_bfloat16 xbf[RPC * 8];    //  2KB bf16 x
    float x2sh[RPC];
    float bitsv[RPC];
    float scr[TPB];
    double dscr[TPB];
    int flag;
};

__device__ __forceinline__ float sqrt_approx(float v) {
    float r; asm("sqrt.approx.f32 %0, %1;" : "=f"(r) : "f"(v)); return r;
}

__device__ __forceinline__ void hmma_16n8k8(float& d0, float& d1, float& d2, float& d3,
                                            uint32_t a0, uint32_t a1, uint32_t b0) {
    asm volatile(
        "mma.sync.aligned.m16n8k8.row.col.f32.bf16.bf16.f32 "
        "{%0,%1,%2,%3}, {%4,%5}, {%6}, {%7,%8,%9,%10};"
        : "=f"(d0), "=f"(d1), "=f"(d2), "=f"(d3)
        : "r"(a0), "r"(a1), "r"(b0),
          "f"(0.0f), "f"(0.0f), "f"(0.0f), "f"(0.0f));
}

__global__ void __launch_bounds__(TPB, 2)
ecvq_kernel(const float* __restrict__ x,
            const float* __restrict__ codebook,
            const float* __restrict__ logits,
            float* __restrict__ out, int B)
{
    extern __shared__ unsigned char smem_raw[];
    Smem* sm = reinterpret_cast<Smem*>(smem_raw);

    const int tid  = threadIdx.x;
    const int cb   = blockIdx.x;
    const int rowBase = blockIdx.y * RPC;

    // ---- log-softmax over logits[cb][:] (identical chain to the proven R2 kernel) ----
    float* scr = sm->scr;
    float4 lv = *reinterpret_cast<const float4*>(logits + (size_t)cb * CSZ + tid * 4);
    float lm = fmaxf(fmaxf(lv.x, lv.y), fmaxf(lv.z, lv.w));
    scr[tid] = lm; __syncthreads();
    #pragma unroll
    for (int off = 128; off > 0; off >>= 1) {
        if (tid < off) scr[tid] = fmaxf(scr[tid], scr[tid + off]);
        __syncthreads();
    }
    const float mx = scr[0]; __syncthreads();
    // min-tree for const-logits detection
    float lmn = fminf(fminf(lv.x, lv.y), fminf(lv.z, lv.w));
    scr[tid] = lmn; __syncthreads();
    #pragma unroll
    for (int off = 128; off > 0; off >>= 1) {
        if (tid < off) scr[tid] = fminf(scr[tid], scr[tid + off]);
        __syncthreads();
    }
    const bool lc = (scr[0] == mx);   // all logits equal -> L constant
    __syncthreads();
    float es = expf(lv.x - mx) + expf(lv.y - mx) + expf(lv.z - mx) + expf(lv.w - mx);
    scr[tid] = es; __syncthreads();
    #pragma unroll
    for (int off = 128; off > 0; off >>= 1) {
        if (tid < off) scr[tid] += scr[tid + off];
        __syncthreads();
    }
    const float lnS = logf(scr[0]); __syncthreads();

    // ---- stage codebook: exact fp32, bf16, c2, L, p2 ----
    const float INV_LOG2 = 1.4426950408889634f;
    #pragma unroll
    for (int j = 0; j < 4; j++) {
        int s = tid * 4 + j;
        const float4* cp = reinterpret_cast<const float4*>(codebook + ((size_t)cb * CSZ + s) * 8);
        float4 c0 = cp[0], c1 = cp[1];
        sm->craw[2 * s] = c0; sm->craw[2 * s + 1] = c1;
        float q0=c0.x*c0.x,q1=c0.y*c0.y,q2=c0.z*c0.z,q3=c0.w*c0.w;
        float q4=c1.x*c1.x,q5=c1.y*c1.y,q6=c1.z*c1.z,q7=c1.w*c1.w;
        sm->c2arr[s] = ((((((q0+q1)+q2)+q3)+q4)+q5)+q6)+q7;
        float v  = (j==0)?lv.x:(j==1)?lv.y:(j==2)?lv.z:lv.w;
        float p2 = ((v - mx) - lnS) * (-INV_LOG2);
        sm->Lsh[s]  = p2 / 0.005f;
        sm->p2sh[s] = p2;
        __nv_bfloat16* cb16 = &sm->cbf[s * 8];
        cb16[0]=__float2bfloat16_rn(c0.x); cb16[1]=__float2bfloat16_rn(c0.y);
        cb16[2]=__float2bfloat16_rn(c0.z); cb16[3]=__float2bfloat16_rn(c0.w);
        cb16[4]=__float2bfloat16_rn(c1.x); cb16[5]=__float2bfloat16_rn(c1.y);
        cb16[6]=__float2bfloat16_rn(c1.z); cb16[7]=__float2bfloat16_rn(c1.w);
    }

    // ---- stage x rows ----
    if (tid < RPC) {
        int grow = rowBase + tid;
        const float4* xpp = reinterpret_cast<const float4*>(x + (size_t)grow * (CBN * 8) + cb * 8);
        float4 p0 = xpp[0], p1 = xpp[1];
        sm->xfp[2 * tid] = p0; sm->xfp[2 * tid + 1] = p1;
        float q0=p0.x*p0.x,q1=p0.y*p0.y,q2=p0.z*p0.z,q3=p0.w*p0.w;
        float q4=p1.x*p1.x,q5=p1.y*p1.y,q6=p1.z*p1.z,q7=p1.w*p1.w;
        sm->x2sh[tid] = ((((((q0+q1)+q2)+q3)+q4)+q5)+q6)+q7;
        __nv_bfloat16* xb = &sm->xbf[tid * 8];
        xb[0]=__float2bfloat16_rn(p0.x); xb[1]=__float2bfloat16_rn(p0.y);
        xb[2]=__float2bfloat16_rn(p0.z); xb[3]=__float2bfloat16_rn(p0.w);
        xb[4]=__float2bfloat16_rn(p1.x); xb[5]=__float2bfloat16_rn(p1.y);
        xb[6]=__float2bfloat16_rn(p1.z); xb[7]=__float2bfloat16_rn(p1.w);
    }
    __syncthreads();

    // ---- per-warp MMA scan: warp owns 16 rows x 1024 cands ----
    const int warp = tid >> 5, lane = tid & 31;
    const int g = lane >> 2, t = lane & 3;
    const int r0 = warp * 16 + g, r1 = r0 + 8;

    uint32_t a0 = *reinterpret_cast<const uint32_t*>(&sm->xbf[r0 * 8 + t * 2]);
    uint32_t a1 = *reinterpret_cast<const uint32_t*>(&sm->xbf[r1 * 8 + t * 2]);
    const float x2_0 = sm->x2sh[r0], x2_1 = sm->x2sh[r1];
    const float4 xa0 = sm->xfp[2 * r0], xa1 = sm->xfp[2 * r0 + 1];
    const float4 xb0 = sm->xfp[2 * r1], xb1 = sm->xfp[2 * r1 + 1];
    const float Lc = sm->Lsh[0];

    float bv0 = __int_as_float(0x7f800000), bv1 = bv0;
    int   bi0 = 0, bi1 = 0;
    float thr0 = bv0, thr1 = bv0;   // +inf: first candidate always rescored

    auto rescue = [&](int s, float c2s, const float4& pa, const float4& pb,
                      float x2r, float& bv, int& bi, float& thr) {
        float4 ca = sm->craw[2 * s], cbv = sm->craw[2 * s + 1];
        float xc = pa.x * ca.x;
        xc = fmaf(pa.y, ca.y, xc); xc = fmaf(pa.z, ca.z, xc); xc = fmaf(pa.w, ca.w, xc);
        xc = fmaf(pb.x, cbv.x, xc); xc = fmaf(pb.y, cbv.y, xc);
        xc = fmaf(pb.z, cbv.z, xc); xc = fmaf(pb.w, cbv.w, xc);
        float d2 = fmaf(-2.0f, xc, x2r) + c2s;
        float Ls = lc ? Lc : sm->Lsh[s];
        float val = sqrt_approx(fmaxf(d2, 0.0f)) + Ls;
        if (val < bv) {
            bv = val; bi = s;
            if (lc) {
                float tt = bv - Lc;
                thr = (tt > 0.0f) ? (tt * tt - x2r + EPS) : -3.0e38f;
            }
        }
    };

    #pragma unroll 2
    for (int nt = 0; nt < 128; nt++) {
        const int base = nt * 8;
        uint32_t b0 = *reinterpret_cast<const uint32_t*>(&sm->cbf[(base + g) * 8 + t * 2]);
        float2 c2p = *reinterpret_cast<const float2*>(&sm->c2arr[base + 2 * t]);
        float d0, d1, d2r, d3;
        hmma_16n8k8(d0, d1, d2r, d3, a0, a1, b0);
        float s00 = fmaf(-2.0f, d0,  c2p.x);
        float s01 = fmaf(-2.0f, d1,  c2p.y);
        float s10 = fmaf(-2.0f, d2r, c2p.x);
        float s11 = fmaf(-2.0f, d3,  c2p.y);
        if (s00 < thr0) rescue(base + 2 * t,     c2p.x, xa0, xa1, x2_0, bv0, bi0, thr0);
        if (s01 < thr0) rescue(base + 2 * t + 1, c2p.y, xa0, xa1, x2_0, bv0, bi0, thr0);
        if (s10 < thr1) rescue(base + 2 * t,     c2p.x, xb0, xb1, x2_1, bv1, bi1, thr1);
        if (s11 < thr1) rescue(base + 2 * t + 1, c2p.y, xb0, xb1, x2_1, bv1, bi1, thr1);
    }

    // ---- reduce across the 4 lanes sharing each row (tie -> smaller index) ----
    #pragma unroll
    for (int mref = 1; mref <= 2; mref <<= 1) {
        float ov0 = __shfl_xor_sync(0xffffffff, bv0, mref);
        int   oi0 = __shfl_xor_sync(0xffffffff, bi0, mref);
        if (ov0 < bv0 || (ov0 == bv0 && oi0 < bi0)) { bv0 = ov0; bi0 = oi0; }
        float ov1 = __shfl_xor_sync(0xffffffff, bv1, mref);
        int   oi1 = __shfl_xor_sync(0xffffffff, bi1, mref);
        if (ov1 < bv1 || (ov1 == bv1 && oi1 < bi1)) { bv1 = ov1; bi1 = oi1; }
    }

    if (t == 0) {
        int grow0 = rowBase + r0, grow1 = rowBase + r1;
        float4* op0 = reinterpret_cast<float4*>(out + (size_t)grow0 * (CBN * 8) + cb * 8);
        op0[0] = sm->craw[2 * bi0]; op0[1] = sm->craw[2 * bi0 + 1];
        float4* op1 = reinterpret_cast<float4*>(out + (size_t)grow1 * (CBN * 8) + cb * 8);
        op1[0] = sm->craw[2 * bi1]; op1[1] = sm->craw[2 * bi1 + 1];
        size_t ixBase = (size_t)B * (CBN * 8) + 1;
        out[ixBase + (size_t)grow0 * CBN + cb] = (float)bi0;
        out[ixBase + (size_t)grow1 * CBN + cb] = (float)bi1;
        sm->bitsv[r0] = sm->p2sh[bi0];
        sm->bitsv[r1] = sm->p2sh[bi1];
    }
    __syncthreads();

    // ---- per-CTA deterministic bits partial ----
    double* bd = sm->dscr;
    bd[tid] = (tid < RPC) ? (double)sm->bitsv[tid] : 0.0;
    __syncthreads();
    #pragma unroll
    for (int off = 128; off > 0; off >>= 1) {
        if (tid < off) bd[tid] += bd[tid + off];
        __syncthreads();
    }
    const int nCTA = gridDim.x * gridDim.y;
    if (tid == 0) {
        g_part[blockIdx.x * gridDim.y + blockIdx.y] = bd[0];
        __threadfence();
        unsigned int old = atomicAdd(&g_ctr, 1u);
        sm->flag = (old == (unsigned)(nCTA - 1)) ? 1 : 0;
    }
    __syncthreads();

    // ---- last CTA: deterministic final sum ----
    if (sm->flag) {
        double acc = 0.0;
        for (int i = tid; i < nCTA; i += TPB)
            acc += ((volatile double*)g_part)[i];
        bd[tid] = acc;
        __syncthreads();
        #pragma unroll
        for (int off = 128; off > 0; off >>= 1) {
            if (tid < off) bd[tid] += bd[tid + off];
            __syncthreads();
        }
        if (tid == 0) {
            out[(size_t)B * (CBN * 8)] = (float)bd[0];
            g_ctr = 0;   // reset for next graph replay (deterministic)
        }
    }
}

extern "C" void kernel_launch(void* const* d_in, const int* in_sizes, int n_in,
                              void* d_out, int out_size)
{
    const float* x = nullptr; const float* codebook = nullptr; const float* logits = nullptr;
    int B = 0;
    for (int i = 0; i < n_in; i++) {
        if (in_sizes[i] == CBN * CSZ)          logits   = (const float*)d_in[i];
        else if (in_sizes[i] == CBN * CSZ * 8) codebook = (const float*)d_in[i];
        else { x = (const float*)d_in[i]; B = in_sizes[i] / (CBN * 8); }
    }
    float* out = (float*)d_out;

    size_t smem = sizeof(Smem);
    cudaFuncSetAttribute(ecvq_kernel,
                         cudaFuncAttributeMaxDynamicSharedMemorySize, (int)smem);

    dim3 grid(CBN, B / RPC);
    ecvq_kernel<<<grid, TPB, smem>>>(x, codebook, logits, out, B);
}

// round 7
// speedup vs baseline: 1.1433x; 1.1433x over previous
#include <cuda_runtime.h>
#include <cuda_bf16.h>
#include <stdint.h>
#include <math.h>

#define CBN 6
#define CSZ 1024
#define TPB 256
#define RPC 256          // rows per CTA
#define EPS 0.5f         // rescue window: >= 2*max bf16 score err + tie window (~0.11), 5x margin

__device__ double g_part[CBN * 128];
__device__ unsigned int g_ctr = 0;

struct __align__(16) Smem {
    uint2  bfrag[CSZ * 4];       // 32KB  per cand: k-interleaved [k2t,k2t+1 | k2t+8,k2t+9]
    float4 craw[2 * CSZ];        // 32KB  exact fp32 codebook
    float  c2arr[CSZ];           //  4KB  exact c2
    float  Lsh[CSZ];             //  4KB  L = log2pmf/lambda
    float  p2sh[CSZ];            //  4KB  log2pmf
    float4 xfp[2 * RPC];         //  8KB  exact fp32 x
    unsigned short xaf[RPC * 8]; //  4KB  bf16(-2x) a-frags
    float  x2sh[RPC];            //  1KB
    float  bitsv[RPC];           //  1KB
    float  scr[TPB];             //  1KB
    double dscr[TPB];            //  2KB
    int    flag;
};

__device__ __forceinline__ float sqrt_approx(float v) {
    float r; asm("sqrt.approx.f32 %0, %1;" : "=f"(r) : "f"(v)); return r;
}

__device__ __forceinline__ void hmma16816(float& d0, float& d1, float& d2, float& d3,
                                          uint32_t a0, uint32_t a1, uint32_t a2, uint32_t a3,
                                          uint32_t b0, uint32_t b1) {
    asm volatile(
        "mma.sync.aligned.m16n8k16.row.col.f32.bf16.bf16.f32 "
        "{%0,%1,%2,%3}, {%4,%5,%6,%7}, {%8,%9}, {%10,%11,%12,%13};"
        : "=f"(d0), "=f"(d1), "=f"(d2), "=f"(d3)
        : "r"(a0), "r"(a1), "r"(a2), "r"(a3), "r"(b0), "r"(b1),
          "f"(0.0f), "f"(0.0f), "f"(0.0f), "f"(0.0f));
}

__global__ void __launch_bounds__(TPB, 2)
ecvq_kernel(const float* __restrict__ x,
            const float* __restrict__ codebook,
            const float* __restrict__ logits,
            float* __restrict__ out, int B)
{
    extern __shared__ unsigned char smem_raw[];
    Smem* sm = reinterpret_cast<Smem*>(smem_raw);

    const int tid = threadIdx.x;
    const int cb  = blockIdx.x;
    const int rowBase = blockIdx.y * RPC;
    const float FINF = __int_as_float(0x7f800000);

    // ---- log-softmax over logits[cb][:] (proven chain) ----
    float* scr = sm->scr;
    float4 lv = *reinterpret_cast<const float4*>(logits + (size_t)cb * CSZ + tid * 4);
    float lm = fmaxf(fmaxf(lv.x, lv.y), fmaxf(lv.z, lv.w));
    scr[tid] = lm; __syncthreads();
    #pragma unroll
    for (int off = 128; off > 0; off >>= 1) {
        if (tid < off) scr[tid] = fmaxf(scr[tid], scr[tid + off]);
        __syncthreads();
    }
    const float mx = scr[0]; __syncthreads();
    float lmn = fminf(fminf(lv.x, lv.y), fminf(lv.z, lv.w));
    scr[tid] = lmn; __syncthreads();
    #pragma unroll
    for (int off = 128; off > 0; off >>= 1) {
        if (tid < off) scr[tid] = fminf(scr[tid], scr[tid + off]);
        __syncthreads();
    }
    const bool lc = (scr[0] == mx);   // constant logits -> L constant
    __syncthreads();
    float es = expf(lv.x - mx) + expf(lv.y - mx) + expf(lv.z - mx) + expf(lv.w - mx);
    scr[tid] = es; __syncthreads();
    #pragma unroll
    for (int off = 128; off > 0; off >>= 1) {
        if (tid < off) scr[tid] += scr[tid + off];
        __syncthreads();
    }
    const float lnS = logf(scr[0]); __syncthreads();

    // ---- stage codebook: bfrag (bf16 + folded c2), craw, c2, L, p2 ----
    const float INV_LOG2 = 1.4426950408889634f;
    #pragma unroll
    for (int j = 0; j < 4; j++) {
        int s = tid * 4 + j;
        const float4* cp = reinterpret_cast<const float4*>(codebook + ((size_t)cb * CSZ + s) * 8);
        float4 c0 = cp[0], c1 = cp[1];
        sm->craw[2 * s] = c0; sm->craw[2 * s + 1] = c1;
        float q0=c0.x*c0.x,q1=c0.y*c0.y,q2=c0.z*c0.z,q3=c0.w*c0.w;
        float q4=c1.x*c1.x,q5=c1.y*c1.y,q6=c1.z*c1.z,q7=c1.w*c1.w;
        float c2 = ((((((q0+q1)+q2)+q3)+q4)+q5)+q6)+q7;
        sm->c2arr[s] = c2;
        float v  = (j==0)?lv.x:(j==1)?lv.y:(j==2)?lv.z:lv.w;
        float p2 = ((v - mx) - lnS) * (-INV_LOG2);
        sm->Lsh[s]  = p2 / 0.005f;
        sm->p2sh[s] = p2;
        unsigned short e0 = __bfloat16_as_ushort(__float2bfloat16_rn(c0.x));
        unsigned short e1 = __bfloat16_as_ushort(__float2bfloat16_rn(c0.y));
        unsigned short e2 = __bfloat16_as_ushort(__float2bfloat16_rn(c0.z));
        unsigned short e3 = __bfloat16_as_ushort(__float2bfloat16_rn(c0.w));
        unsigned short e4 = __bfloat16_as_ushort(__float2bfloat16_rn(c1.x));
        unsigned short e5 = __bfloat16_as_ushort(__float2bfloat16_rn(c1.y));
        unsigned short e6 = __bfloat16_as_ushort(__float2bfloat16_rn(c1.z));
        unsigned short e7 = __bfloat16_as_ushort(__float2bfloat16_rn(c1.w));
        unsigned short c2b = __bfloat16_as_ushort(__float2bfloat16_rn(c2));
        uint2* bq = &sm->bfrag[s * 4];
        bq[0] = make_uint2((uint32_t)e0 | ((uint32_t)e1 << 16), (uint32_t)c2b); // k0,k1 | k8=c2,k9=0
        bq[1] = make_uint2((uint32_t)e2 | ((uint32_t)e3 << 16), 0u);
        bq[2] = make_uint2((uint32_t)e4 | ((uint32_t)e5 << 16), 0u);
        bq[3] = make_uint2((uint32_t)e6 | ((uint32_t)e7 << 16), 0u);
    }

    // ---- stage x: a-frags bf16(-2x), exact fp32, x2 ----
    {
        int grow = rowBase + tid;
        const float4* xpp = reinterpret_cast<const float4*>(x + (size_t)grow * (CBN * 8) + cb * 8);
        float4 p0 = xpp[0], p1 = xpp[1];
        sm->xfp[2 * tid] = p0; sm->xfp[2 * tid + 1] = p1;
        float q0=p0.x*p0.x,q1=p0.y*p0.y,q2=p0.z*p0.z,q3=p0.w*p0.w;
        float q4=p1.x*p1.x,q5=p1.y*p1.y,q6=p1.z*p1.z,q7=p1.w*p1.w;
        sm->x2sh[tid] = ((((((q0+q1)+q2)+q3)+q4)+q5)+q6)+q7;
        unsigned short* xa = &sm->xaf[tid * 8];
        xa[0]=__bfloat16_as_ushort(__float2bfloat16_rn(-2.0f*p0.x));
        xa[1]=__bfloat16_as_ushort(__float2bfloat16_rn(-2.0f*p0.y));
        xa[2]=__bfloat16_as_ushort(__float2bfloat16_rn(-2.0f*p0.z));
        xa[3]=__bfloat16_as_ushort(__float2bfloat16_rn(-2.0f*p0.w));
        xa[4]=__bfloat16_as_ushort(__float2bfloat16_rn(-2.0f*p1.x));
        xa[5]=__bfloat16_as_ushort(__float2bfloat16_rn(-2.0f*p1.y));
        xa[6]=__bfloat16_as_ushort(__float2bfloat16_rn(-2.0f*p1.z));
        xa[7]=__bfloat16_as_ushort(__float2bfloat16_rn(-2.0f*p1.w));
    }
    __syncthreads();

    // ---- warp tiling: rows rA0,rA1 (0..127) and rB0,rB1 (128..255) ----
    const int warp = tid >> 5, lane = tid & 31;
    const int g = lane >> 2, t = lane & 3;
    const int rA0 = warp * 16 + g,       rA1 = rA0 + 8;
    const int rB0 = 128 + warp * 16 + g, rB1 = rB0 + 8;

    const uint32_t aA0 = *reinterpret_cast<const uint32_t*>(&sm->xaf[rA0 * 8 + t * 2]);
    const uint32_t aA1 = *reinterpret_cast<const uint32_t*>(&sm->xaf[rA1 * 8 + t * 2]);
    const uint32_t aB0 = *reinterpret_cast<const uint32_t*>(&sm->xaf[rB0 * 8 + t * 2]);
    const uint32_t aB1 = *reinterpret_cast<const uint32_t*>(&sm->xaf[rB1 * 8 + t * 2]);
    const uint32_t ac  = (t == 0) ? 0x00003F80u : 0u;   // bf16(1.0) at k8

    const char* bp = reinterpret_cast<const char*>(sm->bfrag) + g * 32 + t * 8;

    // ================= PASS 1: branchless min of s = c2 - 2xc =================
    float mA0 = FINF, mA1 = FINF, mB0 = FINF, mB1 = FINF;
    #pragma unroll 4
    for (int nt = 0; nt < 128; nt++) {
        uint2 bq = *reinterpret_cast<const uint2*>(bp + nt * 256);
        float dA0, dA1, dA2, dA3, dB0, dB1, dB2, dB3;
        hmma16816(dA0, dA1, dA2, dA3, aA0, aA1, ac, ac, bq.x, bq.y);
        hmma16816(dB0, dB1, dB2, dB3, aB0, aB1, ac, ac, bq.x, bq.y);
        mA0 = fminf(mA0, fminf(dA0, dA1));
        mA1 = fminf(mA1, fminf(dA2, dA3));
        mB0 = fminf(mB0, fminf(dB0, dB1));
        mB1 = fminf(mB1, fminf(dB2, dB3));
    }
    mA0 = fminf(mA0, __shfl_xor_sync(0xffffffffu, mA0, 1));
    mA0 = fminf(mA0, __shfl_xor_sync(0xffffffffu, mA0, 2));
    mA1 = fminf(mA1, __shfl_xor_sync(0xffffffffu, mA1, 1));
    mA1 = fminf(mA1, __shfl_xor_sync(0xffffffffu, mA1, 2));
    mB0 = fminf(mB0, __shfl_xor_sync(0xffffffffu, mB0, 1));
    mB0 = fminf(mB0, __shfl_xor_sync(0xffffffffu, mB0, 2));
    mB1 = fminf(mB1, __shfl_xor_sync(0xffffffffu, mB1, 1));
    mB1 = fminf(mB1, __shfl_xor_sync(0xffffffffu, mB1, 2));

    const float thrA0 = lc ? mA0 + EPS : FINF;
    const float thrA1 = lc ? mA1 + EPS : FINF;
    const float thrB0 = lc ? mB0 + EPS : FINF;
    const float thrB1 = lc ? mB1 + EPS : FINF;

    // exact rescore (bit-exact chain from the R2/R5 proven kernels; rare)
    auto rescue = [&](int s, int r, float& bv, int& bi) {
        float4 ca = sm->craw[2 * s], cv = sm->craw[2 * s + 1];
        float4 pa = sm->xfp[2 * r],  pb = sm->xfp[2 * r + 1];
        float xc = pa.x * ca.x;
        xc = fmaf(pa.y, ca.y, xc); xc = fmaf(pa.z, ca.z, xc); xc = fmaf(pa.w, ca.w, xc);
        xc = fmaf(pb.x, cv.x, xc); xc = fmaf(pb.y, cv.y, xc);
        xc = fmaf(pb.z, cv.z, xc); xc = fmaf(pb.w, cv.w, xc);
        float d2 = fmaf(-2.0f, xc, sm->x2sh[r]) + sm->c2arr[s];
        float val = sqrt_approx(fmaxf(d2, 0.0f)) + sm->Lsh[s];
        if (val < bv) { bv = val; bi = s; }
    };

    // ================= PASS 2: fixed-threshold exact rescue =================
    float bvA0 = FINF, bvA1 = FINF, bvB0 = FINF, bvB1 = FINF;
    int   biA0 = 0,    biA1 = 0,    biB0 = 0,    biB1 = 0;
    #pragma unroll 1
    for (int nt = 0; nt < 128; nt++) {
        uint2 bq = *reinterpret_cast<const uint2*>(bp + nt * 256);
        float dA0, dA1, dA2, dA3, dB0, dB1, dB2, dB3;
        hmma16816(dA0, dA1, dA2, dA3, aA0, aA1, ac, ac, bq.x, bq.y);
        hmma16816(dB0, dB1, dB2, dB3, aB0, aB1, ac, ac, bq.x, bq.y);
        bool any = (fminf(dA0, dA1) < thrA0) | (fminf(dA2, dA3) < thrA1)
                 | (fminf(dB0, dB1) < thrB0) | (fminf(dB2, dB3) < thrB1);
        if (any) {
            int s0 = nt * 8 + 2 * t, s1 = s0 + 1;
            if (dA0 < thrA0) rescue(s0, rA0, bvA0, biA0);
            if (dA1 < thrA0) rescue(s1, rA0, bvA0, biA0);
            if (dA2 < thrA1) rescue(s0, rA1, bvA1, biA1);
            if (dA3 < thrA1) rescue(s1, rA1, bvA1, biA1);
            if (dB0 < thrB0) rescue(s0, rB0, bvB0, biB0);
            if (dB1 < thrB0) rescue(s1, rB0, bvB0, biB0);
            if (dB2 < thrB1) rescue(s0, rB1, bvB1, biB1);
            if (dB3 < thrB1) rescue(s1, rB1, bvB1, biB1);
        }
    }

    // ---- cross-lane (t) reduce with lowest-index tie-break ----
    #pragma unroll
    for (int mref = 1; mref <= 2; mref <<= 1) {
        float ov; int oi;
        ov = __shfl_xor_sync(0xffffffffu, bvA0, mref); oi = __shfl_xor_sync(0xffffffffu, biA0, mref);
        if (ov < bvA0 || (ov == bvA0 && oi < biA0)) { bvA0 = ov; biA0 = oi; }
        ov = __shfl_xor_sync(0xffffffffu, bvA1, mref); oi = __shfl_xor_sync(0xffffffffu, biA1, mref);
        if (ov < bvA1 || (ov == bvA1 && oi < biA1)) { bvA1 = ov; biA1 = oi; }
        ov = __shfl_xor_sync(0xffffffffu, bvB0, mref); oi = __shfl_xor_sync(0xffffffffu, biB0, mref);
        if (ov < bvB0 || (ov == bvB0 && oi < biB0)) { bvB0 = ov; biB0 = oi; }
        ov = __shfl_xor_sync(0xffffffffu, bvB1, mref); oi = __shfl_xor_sync(0xffffffffu, biB1, mref);
        if (ov < bvB1 || (ov == bvB1 && oi < biB1)) { bvB1 = ov; biB1 = oi; }
    }

    if (t == 0) {
        const size_t ixBase = (size_t)B * (CBN * 8) + 1;
        int rr[4]  = {rA0, rA1, rB0, rB1};
        int bb[4]  = {biA0, biA1, biB0, biB1};
        #pragma unroll
        for (int q = 0; q < 4; q++) {
            int r = rr[q], bi = bb[q];
            int grow = rowBase + r;
            float4* op = reinterpret_cast<float4*>(out + (size_t)grow * (CBN * 8) + cb * 8);
            op[0] = sm->craw[2 * bi];
            op[1] = sm->craw[2 * bi + 1];
            out[ixBase + (size_t)grow * CBN + cb] = (float)bi;
            sm->bitsv[r] = sm->p2sh[bi];
        }
    }
    __syncthreads();

    // ---- per-CTA deterministic bits partial ----
    double* bd = sm->dscr;
    bd[tid] = (double)sm->bitsv[tid];
    __syncthreads();
    #pragma unroll
    for (int off = 128; off > 0; off >>= 1) {
        if (tid < off) bd[tid] += bd[tid + off];
        __syncthreads();
    }
    const int nCTA = gridDim.x * gridDim.y;
    if (tid == 0) {
        g_part[blockIdx.x * gridDim.y + blockIdx.y] = bd[0];
        __threadfence();
        unsigned int old = atomicAdd(&g_ctr, 1u);
        sm->flag = (old == (unsigned)(nCTA - 1)) ? 1 : 0;
    }
    __syncthreads();

    // ---- last CTA: deterministic final bits sum ----
    if (sm->flag) {
        double acc = 0.0;
        for (int i = tid; i < nCTA; i += TPB)
            acc += ((volatile double*)g_part)[i];
        bd[tid] = acc;
        __syncthreads();
        #pragma unroll
        for (int off = 128; off > 0; off >>= 1) {
            if (tid < off) bd[tid] += bd[tid + off];
            __syncthreads();
        }
        if (tid == 0) {
            out[(size_t)B * (CBN * 8)] = (float)bd[0];
            g_ctr = 0;   // reset for next graph replay
        }
    }
}

extern "C" void kernel_launch(void* const* d_in, const int* in_sizes, int n_in,
                              void* d_out, int out_size)
{
    const float* x = nullptr; const float* codebook = nullptr; const float* logits = nullptr;
    int B = 0;
    for (int i = 0; i < n_in; i++) {
        if (in_sizes[i] == CBN * CSZ)          logits   = (const float*)d_in[i];
        else if (in_sizes[i] == CBN * CSZ * 8) codebook = (const float*)d_in[i];
        else { x = (const float*)d_in[i]; B = in_sizes[i] / (CBN * 8); }
    }
    float* out = (float*)d_out;

    size_t smem = sizeof(Smem);
    cudaFuncSetAttribute(ecvq_kernel,
                         cudaFuncAttributeMaxDynamicSharedMemorySize, (int)smem);

    dim3 grid(CBN, B / RPC);
    ecvq_kernel<<<grid, TPB, smem>>>(x, codebook, logits, out, B);
}

// round 8
// speedup vs baseline: 1.2714x; 1.1121x over previous
#include <cuda_runtime.h>
#include <cuda_bf16.h>
#include <stdint.h>
#include <math.h>

#define CBN 6
#define CSZ 1024
#define TPB 256
#define RPC 128          // rows per CTA (16 per warp)
#define EPS 0.5f         // proven rescue window (R7: rel_err 0.0)

// precomputed per-cb tables (prep kernel -> main kernel)
__device__ uint2  g_bfrag[CBN * CSZ * 4];   // 192KB b-frags (bf16 c + folded bf16 c2)
__device__ float  g_c2[CBN * CSZ];
__device__ float  g_L[CBN * CSZ];
__device__ float  g_p2[CBN * CSZ];
__device__ int    g_lc[CBN];
__device__ double g_part[CBN * 256];
__device__ unsigned int g_ctr = 0;

struct __align__(16) Smem {
    uint2  bfrag[CSZ * 4];       // 32KB
    float  c2arr[CSZ];           //  4KB
    float  Lsh[CSZ];             //  4KB
    float  p2sh[CSZ];            //  4KB
    float4 xfp[2 * RPC];         //  4KB exact fp32 x
    unsigned short xaf[RPC * 8]; //  2KB bf16(-2x) a-frags
    float  x2sh[RPC];            // 0.5KB
    float  bitsv[RPC];           // 0.5KB
    double dscr[TPB];            //  2KB
    int    flag;
};

__device__ __forceinline__ float sqrt_approx(float v) {
    float r; asm("sqrt.approx.f32 %0, %1;" : "=f"(r) : "f"(v)); return r;
}

__device__ __forceinline__ void hmma16816(float& d0, float& d1, float& d2, float& d3,
                                          uint32_t a0, uint32_t a1, uint32_t a2, uint32_t a3,
                                          uint32_t b0, uint32_t b1) {
    asm volatile(
        "mma.sync.aligned.m16n8k16.row.col.f32.bf16.bf16.f32 "
        "{%0,%1,%2,%3}, {%4,%5,%6,%7}, {%8,%9}, {%10,%11,%12,%13};"
        : "=f"(d0), "=f"(d1), "=f"(d2), "=f"(d3)
        : "r"(a0), "r"(a1), "r"(a2), "r"(a3), "r"(b0), "r"(b1),
          "f"(0.0f), "f"(0.0f), "f"(0.0f), "f"(0.0f));
}

// ---------------- prep: per-cb tables (proven numerics chain) ----------------
__global__ void __launch_bounds__(TPB) prep_kernel(
    const float* __restrict__ codebook,
    const float* __restrict__ logits)
{
    __shared__ float scr[TPB];
    const int tid = threadIdx.x;
    const int cb  = blockIdx.x;

    float4 lv = *reinterpret_cast<const float4*>(logits + (size_t)cb * CSZ + tid * 4);
    float lm = fmaxf(fmaxf(lv.x, lv.y), fmaxf(lv.z, lv.w));
    scr[tid] = lm; __syncthreads();
    #pragma unroll
    for (int off = 128; off > 0; off >>= 1) {
        if (tid < off) scr[tid] = fmaxf(scr[tid], scr[tid + off]);
        __syncthreads();
    }
    const float mx = scr[0]; __syncthreads();
    float lmn = fminf(fminf(lv.x, lv.y), fminf(lv.z, lv.w));
    scr[tid] = lmn; __syncthreads();
    #pragma unroll
    for (int off = 128; off > 0; off >>= 1) {
        if (tid < off) scr[tid] = fminf(scr[tid], scr[tid + off]);
        __syncthreads();
    }
    const bool lc = (scr[0] == mx);
    __syncthreads();
    float es = expf(lv.x - mx) + expf(lv.y - mx) + expf(lv.z - mx) + expf(lv.w - mx);
    scr[tid] = es; __syncthreads();
    #pragma unroll
    for (int off = 128; off > 0; off >>= 1) {
        if (tid < off) scr[tid] += scr[tid + off];
        __syncthreads();
    }
    const float lnS = logf(scr[0]);

    const float INV_LOG2 = 1.4426950408889634f;
    #pragma unroll
    for (int j = 0; j < 4; j++) {
        int s = tid * 4 + j;
        const float4* cp = reinterpret_cast<const float4*>(codebook + ((size_t)cb * CSZ + s) * 8);
        float4 c0 = cp[0], c1 = cp[1];
        float q0=c0.x*c0.x,q1=c0.y*c0.y,q2=c0.z*c0.z,q3=c0.w*c0.w;
        float q4=c1.x*c1.x,q5=c1.y*c1.y,q6=c1.z*c1.z,q7=c1.w*c1.w;
        float c2 = ((((((q0+q1)+q2)+q3)+q4)+q5)+q6)+q7;
        float v  = (j==0)?lv.x:(j==1)?lv.y:(j==2)?lv.z:lv.w;
        float p2 = ((v - mx) - lnS) * (-INV_LOG2);
        size_t gi = (size_t)cb * CSZ + s;
        g_c2[gi] = c2;
        g_L[gi]  = p2 / 0.005f;
        g_p2[gi] = p2;
        unsigned short e0 = __bfloat16_as_ushort(__float2bfloat16_rn(c0.x));
        unsigned short e1 = __bfloat16_as_ushort(__float2bfloat16_rn(c0.y));
        unsigned short e2 = __bfloat16_as_ushort(__float2bfloat16_rn(c0.z));
        unsigned short e3 = __bfloat16_as_ushort(__float2bfloat16_rn(c0.w));
        unsigned short e4 = __bfloat16_as_ushort(__float2bfloat16_rn(c1.x));
        unsigned short e5 = __bfloat16_as_ushort(__float2bfloat16_rn(c1.y));
        unsigned short e6 = __bfloat16_as_ushort(__float2bfloat16_rn(c1.z));
        unsigned short e7 = __bfloat16_as_ushort(__float2bfloat16_rn(c1.w));
        unsigned short c2b = __bfloat16_as_ushort(__float2bfloat16_rn(c2));
        uint2* bq = &g_bfrag[gi * 4];
        bq[0] = make_uint2((uint32_t)e0 | ((uint32_t)e1 << 16), (uint32_t)c2b);
        bq[1] = make_uint2((uint32_t)e2 | ((uint32_t)e3 << 16), 0u);
        bq[2] = make_uint2((uint32_t)e4 | ((uint32_t)e5 << 16), 0u);
        bq[3] = make_uint2((uint32_t)e6 | ((uint32_t)e7 << 16), 0u);
    }
    if (tid == 0) g_lc[cb] = lc ? 1 : 0;
}

// ---------------- main ----------------
__global__ void __launch_bounds__(TPB, 4)
ecvq_kernel(const float* __restrict__ x,
            const float* __restrict__ codebook,
            float* __restrict__ out, int B)
{
    extern __shared__ unsigned char smem_raw[];
    Smem* sm = reinterpret_cast<Smem*>(smem_raw);

    const int tid = threadIdx.x;
    const int cb  = blockIdx.x;
    const int rowBase = blockIdx.y * RPC;
    const float FINF = __int_as_float(0x7f800000);

    // ---- copy per-cb tables from gmem ----
    {
        const uint4* src = reinterpret_cast<const uint4*>(&g_bfrag[(size_t)cb * CSZ * 4]);
        uint4* dst = reinterpret_cast<uint4*>(sm->bfrag);
        #pragma unroll
        for (int i = 0; i < 8; i++) dst[tid + i * TPB] = src[tid + i * TPB];
        const size_t gb = (size_t)cb * CSZ;
        #pragma unroll
        for (int i = 0; i < 4; i++) {
            int s = tid + i * TPB;
            sm->c2arr[s] = g_c2[gb + s];
            sm->Lsh[s]   = g_L[gb + s];
            sm->p2sh[s]  = g_p2[gb + s];
        }
    }
    const bool lc = (g_lc[cb] != 0);

    // ---- stage x: a-frags bf16(-2x), exact fp32, x2 ----
    if (tid < RPC) {
        int grow = rowBase + tid;
        const float4* xpp = reinterpret_cast<const float4*>(x + (size_t)grow * (CBN * 8) + cb * 8);
        float4 p0 = xpp[0], p1 = xpp[1];
        sm->xfp[2 * tid] = p0; sm->xfp[2 * tid + 1] = p1;
        float q0=p0.x*p0.x,q1=p0.y*p0.y,q2=p0.z*p0.z,q3=p0.w*p0.w;
        float q4=p1.x*p1.x,q5=p1.y*p1.y,q6=p1.z*p1.z,q7=p1.w*p1.w;
        sm->x2sh[tid] = ((((((q0+q1)+q2)+q3)+q4)+q5)+q6)+q7;
        unsigned short* xa = &sm->xaf[tid * 8];
        xa[0]=__bfloat16_as_ushort(__float2bfloat16_rn(-2.0f*p0.x));
        xa[1]=__bfloat16_as_ushort(__float2bfloat16_rn(-2.0f*p0.y));
        xa[2]=__bfloat16_as_ushort(__float2bfloat16_rn(-2.0f*p0.z));
        xa[3]=__bfloat16_as_ushort(__float2bfloat16_rn(-2.0f*p0.w));
        xa[4]=__bfloat16_as_ushort(__float2bfloat16_rn(-2.0f*p1.x));
        xa[5]=__bfloat16_as_ushort(__float2bfloat16_rn(-2.0f*p1.y));
        xa[6]=__bfloat16_as_ushort(__float2bfloat16_rn(-2.0f*p1.z));
        xa[7]=__bfloat16_as_ushort(__float2bfloat16_rn(-2.0f*p1.w));
    }
    __syncthreads();

    // ---- warp tiling: each warp owns 16 rows ----
    const int warp = tid >> 5, lane = tid & 31;
    const int g = lane >> 2, t = lane & 3;
    const int r0 = warp * 16 + g, r1 = r0 + 8;

    const uint32_t a0 = *reinterpret_cast<const uint32_t*>(&sm->xaf[r0 * 8 + t * 2]);
    const uint32_t a1 = *reinterpret_cast<const uint32_t*>(&sm->xaf[r1 * 8 + t * 2]);
    const uint32_t ac = (t == 0) ? 0x00003F80u : 0u;   // bf16(1.0) at k8

    const char* bp = reinterpret_cast<const char*>(sm->bfrag) + g * 32 + t * 8;

    // ============ PASS 1: branchless min of score = c2 - 2xc ============
    float m0 = FINF, m1 = FINF;
    #pragma unroll 8
    for (int nt = 0; nt < 128; nt++) {
        uint2 bq = *reinterpret_cast<const uint2*>(bp + nt * 256);
        float d0, d1, d2, d3;
        hmma16816(d0, d1, d2, d3, a0, a1, ac, ac, bq.x, bq.y);
        m0 = fminf(m0, fminf(d0, d1));
        m1 = fminf(m1, fminf(d2, d3));
    }
    m0 = fminf(m0, __shfl_xor_sync(0xffffffffu, m0, 1));
    m0 = fminf(m0, __shfl_xor_sync(0xffffffffu, m0, 2));
    m1 = fminf(m1, __shfl_xor_sync(0xffffffffu, m1, 1));
    m1 = fminf(m1, __shfl_xor_sync(0xffffffffu, m1, 2));

    const float thr0 = lc ? m0 + EPS : FINF;
    const float thr1 = lc ? m1 + EPS : FINF;

    // exact rescore (bit-exact proven chain)
    auto rescue = [&](int s, int r, float& bv, int& bi) {
        const float4* cp = reinterpret_cast<const float4*>(codebook + ((size_t)cb * CSZ + s) * 8);
        float4 ca = __ldg(cp), cv = __ldg(cp + 1);
        float4 pa = sm->xfp[2 * r], pb = sm->xfp[2 * r + 1];
        float xc = pa.x * ca.x;
        xc = fmaf(pa.y, ca.y, xc); xc = fmaf(pa.z, ca.z, xc); xc = fmaf(pa.w, ca.w, xc);
        xc = fmaf(pb.x, cv.x, xc); xc = fmaf(pb.y, cv.y, xc);
        xc = fmaf(pb.z, cv.z, xc); xc = fmaf(pb.w, cv.w, xc);
        float d2 = fmaf(-2.0f, xc, sm->x2sh[r]) + sm->c2arr[s];
        float val = sqrt_approx(fmaxf(d2, 0.0f)) + sm->Lsh[s];
        if (val < bv) { bv = val; bi = s; }
    };

    // ============ PASS 2: fixed-threshold exact rescue ============
    float bv0 = FINF, bv1 = FINF;
    int   bi0 = 0,    bi1 = 0;
    #pragma unroll 2
    for (int nt = 0; nt < 128; nt++) {
        uint2 bq = *reinterpret_cast<const uint2*>(bp + nt * 256);
        float d0, d1, d2, d3;
        hmma16816(d0, d1, d2, d3, a0, a1, ac, ac, bq.x, bq.y);
        bool anyT = (fminf(d0, d1) < thr0) | (fminf(d2, d3) < thr1);
        if (__ballot_sync(0xffffffffu, anyT)) {
            int s0 = nt * 8 + 2 * t, s1 = s0 + 1;
            if (d0 < thr0) rescue(s0, r0, bv0, bi0);
            if (d1 < thr0) rescue(s1, r0, bv0, bi0);
            if (d2 < thr1) rescue(s0, r1, bv1, bi1);
            if (d3 < thr1) rescue(s1, r1, bv1, bi1);
        }
    }

    // ---- cross-lane reduce (lowest-index ties) ----
    #pragma unroll
    for (int mref = 1; mref <= 2; mref <<= 1) {
        float ov; int oi;
        ov = __shfl_xor_sync(0xffffffffu, bv0, mref); oi = __shfl_xor_sync(0xffffffffu, bi0, mref);
        if (ov < bv0 || (ov == bv0 && oi < bi0)) { bv0 = ov; bi0 = oi; }
        ov = __shfl_xor_sync(0xffffffffu, bv1, mref); oi = __shfl_xor_sync(0xffffffffu, bi1, mref);
        if (ov < bv1 || (ov == bv1 && oi < bi1)) { bv1 = ov; bi1 = oi; }
    }

    if (t == 0) {
        const size_t ixBase = (size_t)B * (CBN * 8) + 1;
        int rr[2] = {r0, r1};
        int bb[2] = {bi0, bi1};
        #pragma unroll
        for (int q = 0; q < 2; q++) {
            int r = rr[q], bi = bb[q];
            int grow = rowBase + r;
            const float4* cp = reinterpret_cast<const float4*>(codebook + ((size_t)cb * CSZ + bi) * 8);
            float4* op = reinterpret_cast<float4*>(out + (size_t)grow * (CBN * 8) + cb * 8);
            op[0] = __ldg(cp);
            op[1] = __ldg(cp + 1);
            out[ixBase + (size_t)grow * CBN + cb] = (float)bi;
            sm->bitsv[r] = sm->p2sh[bi];
        }
    }
    __syncthreads();

    // ---- per-CTA deterministic bits partial ----
    double* bd = sm->dscr;
    bd[tid] = (tid < RPC) ? (double)sm->bitsv[tid] : 0.0;
    __syncthreads();
    #pragma unroll
    for (int off = 128; off > 0; off >>= 1) {
        if (tid < off) bd[tid] += bd[tid + off];
        __syncthreads();
    }
    const int nCTA = gridDim.x * gridDim.y;
    if (tid == 0) {
        g_part[blockIdx.x * gridDim.y + blockIdx.y] = bd[0];
        __threadfence();
        unsigned int old = atomicAdd(&g_ctr, 1u);
        sm->flag = (old == (unsigned)(nCTA - 1)) ? 1 : 0;
    }
    __syncthreads();

    // ---- last CTA: deterministic final bits sum ----
    if (sm->flag) {
        double acc = 0.0;
        for (int i = tid; i < nCTA; i += TPB)
            acc += ((volatile double*)g_part)[i];
        bd[tid] = acc;
        __syncthreads();
        #pragma unroll
        for (int off = 128; off > 0; off >>= 1) {
            if (tid < off) bd[tid] += bd[tid + off];
            __syncthreads();
        }
        if (tid == 0) {
            out[(size_t)B * (CBN * 8)] = (float)bd[0];
            g_ctr = 0;   // reset for next graph replay
        }
    }
}

extern "C" void kernel_launch(void* const* d_in, const int* in_sizes, int n_in,
                              void* d_out, int out_size)
{
    const float* x = nullptr; const float* codebook = nullptr; const float* logits = nullptr;
    int B = 0;
    for (int i = 0; i < n_in; i++) {
        if (in_sizes[i] == CBN * CSZ)          logits   = (const float*)d_in[i];
        else if (in_sizes[i] == CBN * CSZ * 8) codebook = (const float*)d_in[i];
        else { x = (const float*)d_in[i]; B = in_sizes[i] / (CBN * 8); }
    }
    float* out = (float*)d_out;

    size_t smem = sizeof(Smem);
    cudaFuncSetAttribute(ecvq_kernel,
                         cudaFuncAttributeMaxDynamicSharedMemorySize, (int)smem);

    prep_kernel<<<CBN, TPB>>>(codebook, logits);
    dim3 grid(CBN, B / RPC);
    ecvq_kernel<<<grid, TPB, smem>>>(x, codebook, out, B);
}